// round 15
// baseline (speedup 1.0000x reference)
#include <cuda_runtime.h>
#include <math.h>
#include <string.h>

#define NBATCH 16
#define TLEN   64
#define SLEN   1024
#define SRCD   512
#define TGTD   512
#define NT     1024
#define NS     16384
#define NTS    1048576

typedef unsigned long long u64;

#if defined(__CUDA_ARCH__) && (defined(__CUDA_ARCH_FEAT_SM103_ALL) || defined(__CUDA_ARCH_FEAT_SM100_ALL))
#define HAS_X2 1
#else
#define HAS_X2 0
#endif

// ---------------- device scratch ----------------
__device__ __align__(16) float g_wq[NT*64];            // [1024,64]
__device__ __align__(16) float g_uh[NS*64];            // [16384,64]
__device__ __align__(16) float g_alpha[NTS];           // [16,64,1024]
__device__ __align__(16) float g_yal[NTS];             // [16,64,1024]
__device__ __align__(16) float g_ctxp[2*2*NT*SRCD];    // [ks2][branch][1024][512]
__device__ __align__(16) float g_po_in[NT*TGTD];       // input @ W_out_top   [1024,512]
__device__ __align__(16) float g_po_ctx[2*NT*TGTD];    // ctx_br @ W_out_bot  [2,1024,512]

// ---------------- packed fp32 helpers ----------------
__device__ __forceinline__ void fma2(u64& d, u64 a, u64 b) {
#if HAS_X2
    asm("fma.rn.f32x2 %0, %1, %2, %0;" : "+l"(d) : "l"(a), "l"(b));
#else
    float2 dd, aa, bb;
    memcpy(&dd, &d, 8); memcpy(&aa, &a, 8); memcpy(&bb, &b, 8);
    dd.x = fmaf(aa.x, bb.x, dd.x);
    dd.y = fmaf(aa.y, bb.y, dd.y);
    memcpy(&d, &dd, 8);
#endif
}
__device__ __forceinline__ u64 bcast2(float x) {
    float2 t = make_float2(x, x);
    u64 d; memcpy(&d, &t, 8);
    return d;
}

// ---------------- helpers ----------------
__device__ __forceinline__ float tanh_hw(float x) {
    float y;
    asm("tanh.approx.f32 %0, %1;" : "=f"(y) : "f"(x));
    return y;
}
__device__ __forceinline__ float tanh_acc(float x) {
    float e = __expf(2.0f * x);
    return 1.0f - __fdividef(2.0f, e + 1.0f);
}

// JAX threefry2x32, key=(0,42), partitionable: bits = out0 ^ out1
__device__ __forceinline__ unsigned threefry_bits(unsigned idx) {
    const unsigned ks0 = 0u, ks1 = 42u;
    const unsigned ks2 = 0x1BD11BDAu ^ ks0 ^ ks1;
    unsigned x0 = ks0;
    unsigned x1 = idx + ks1;
#define TF_ROUND(r) { x0 += x1; x1 = (x1 << (r)) | (x1 >> (32 - (r))); x1 ^= x0; }
    TF_ROUND(13) TF_ROUND(15) TF_ROUND(26) TF_ROUND(6)
    x0 += ks1; x1 += ks2 + 1u;
    TF_ROUND(17) TF_ROUND(29) TF_ROUND(16) TF_ROUND(24)
    x0 += ks2; x1 += ks0 + 2u;
    TF_ROUND(13) TF_ROUND(15) TF_ROUND(26) TF_ROUND(6)
    x0 += ks0; x1 += ks1 + 3u;
    TF_ROUND(17) TF_ROUND(29) TF_ROUND(16) TF_ROUND(24)
    x0 += ks1; x1 += ks2 + 4u;
    TF_ROUND(13) TF_ROUND(15) TF_ROUND(26) TF_ROUND(6)
    x0 += ks2; x1 += ks0 + 5u;
#undef TF_ROUND
    return x0 ^ x1;
}

__device__ __forceinline__ float gumbel_noise(unsigned idx) {
    unsigned b = threefry_bits(idx);
    float u = __uint_as_float((b >> 9) | 0x3f800000u) - 1.0f;
    float inner = -__logf(u + 1e-20f) + 1e-20f;
    return -__logf(inner);
}

__device__ __forceinline__ float block_reduce_max(float v, float* sred, int tid) {
    #pragma unroll
    for (int o = 16; o > 0; o >>= 1) v = fmaxf(v, __shfl_xor_sync(0xffffffffu, v, o));
    if ((tid & 31) == 0) sred[tid >> 5] = v;
    __syncthreads();
    float r = sred[0];
    #pragma unroll
    for (int i = 1; i < 8; i++) r = fmaxf(r, sred[i]);
    __syncthreads();
    return r;
}

__device__ __forceinline__ float block_reduce_sum(float v, float* sred, int tid) {
    #pragma unroll
    for (int o = 16; o > 0; o >>= 1) v += __shfl_xor_sync(0xffffffffu, v, o);
    if ((tid & 31) == 0) sred[tid >> 5] = v;
    __syncthreads();
    float r = 0.0f;
    #pragma unroll
    for (int i = 0; i < 8; i++) r += sred[i];
    __syncthreads();
    return r;
}

// 8x8 packed step: acc2[ip][j], rows 2ip,2ip+1 (within thread's 8) x col j(0..7)
__device__ __forceinline__ void mma_step8(u64 acc2[4][8], const float* As_kk,
                                          const float* Bs_kk, int ty, int tx) {
    float af[8], bf[8];
    *(float4*)&af[0] = *(const float4*)(As_kk + ty * 8);
    *(float4*)&af[4] = *(const float4*)(As_kk + ty * 8 + 4);
    *(float4*)&bf[0] = *(const float4*)(Bs_kk + tx * 8);
    *(float4*)&bf[4] = *(const float4*)(Bs_kk + tx * 8 + 4);
    u64 af2[4];
    memcpy(af2, af, 32);
    u64 bf2[8];
    #pragma unroll
    for (int j = 0; j < 8; j++) bf2[j] = bcast2(bf[j]);
    #pragma unroll
    for (int ip = 0; ip < 4; ip++)
        #pragma unroll
        for (int j = 0; j < 8; j++)
            fma2(acc2[ip][j], af2[ip], bf2[j]);
}

// unpack one of 8 rows into two float4s (cols 0..3, 4..7)
__device__ __forceinline__ void acc_row8(const u64 acc2[4][8], int i,
                                         float4& lo, float4& hi) {
    float r[8];
    #pragma unroll
    for (int j = 0; j < 8; j++) {
        float2 t; memcpy(&t, &acc2[i >> 1][j], 8);
        r[j] = (i & 1) ? t.y : t.x;
    }
    lo = make_float4(r[0], r[1], r[2], r[3]);
    hi = make_float4(r[4], r[5], r[6], r[7]);
}

// ================================================================
// K1: projections  C[M,64] = A[M,512] @ W[512,64]  (R14 verbatim, 8x4 FFMA2)
// ================================================================
__device__ __forceinline__ void mma_step(u64 acc2[4][4], const float* As_kk,
                                         const float* Bs_kk, int ty, int tx) {
    float af[8], bf[4];
    *(float4*)&af[0] = *(const float4*)(As_kk + ty * 8);
    *(float4*)&af[4] = *(const float4*)(As_kk + ty * 8 + 4);
    *(float4*)&bf[0] = *(const float4*)(Bs_kk + tx * 4);
    u64 af2[4];
    memcpy(af2, af, 32);
    u64 bf2[4];
    #pragma unroll
    for (int j = 0; j < 4; j++) bf2[j] = bcast2(bf[j]);
    #pragma unroll
    for (int ip = 0; ip < 4; ip++)
        #pragma unroll
        for (int j = 0; j < 4; j++)
            fma2(acc2[ip][j], af2[ip], bf2[j]);
}
__device__ __forceinline__ float4 acc_row(const u64 acc2[4][4], int i) {
    float r[4];
    #pragma unroll
    for (int j = 0; j < 4; j++) {
        float2 t; memcpy(&t, &acc2[i >> 1][j], 8);
        r[j] = (i & 1) ? t.y : t.x;
    }
    return make_float4(r[0], r[1], r[2], r[3]);
}

__global__ void __launch_bounds__(256) proj_kernel(const float* __restrict__ A,
                                                   const float* __restrict__ W,
                                                   float* __restrict__ C) {
    __shared__ __align__(16) float As[2][16][132];
    __shared__ __align__(16) float Bs[2][16][64];
    int tid = threadIdx.x;
    int tx = tid & 15, ty = tid >> 4;
    int m0 = blockIdx.x * 128;
    int kk4 = (tid & 3) * 4, mr = tid >> 2;
    int bcol = (tid & 15) * 4, bk = tid >> 4;

    float4 pa0, pa1, pb;
    pa0 = *(const float4*)(A + (size_t)(m0 + mr) * 512 + kk4);
    pa1 = *(const float4*)(A + (size_t)(m0 + mr + 64) * 512 + kk4);
    pb  = *(const float4*)(W + (size_t)bk * 64 + bcol);
    As[0][kk4 + 0][mr] = pa0.x; As[0][kk4 + 1][mr] = pa0.y;
    As[0][kk4 + 2][mr] = pa0.z; As[0][kk4 + 3][mr] = pa0.w;
    As[0][kk4 + 0][mr + 64] = pa1.x; As[0][kk4 + 1][mr + 64] = pa1.y;
    As[0][kk4 + 2][mr + 64] = pa1.z; As[0][kk4 + 3][mr + 64] = pa1.w;
    *(float4*)&Bs[0][bk][bcol] = pb;

    u64 acc2[4][4];
    #pragma unroll
    for (int i = 0; i < 4; i++)
        #pragma unroll
        for (int j = 0; j < 4; j++) acc2[i][j] = 0ull;

    const int NTILES = 32;
    #pragma unroll 1
    for (int t = 0; t < NTILES; t++) {
        __syncthreads();
        int cur = t & 1;
        if (t + 1 < NTILES) {
            int k0 = (t + 1) * 16;
            pa0 = *(const float4*)(A + (size_t)(m0 + mr) * 512 + k0 + kk4);
            pa1 = *(const float4*)(A + (size_t)(m0 + mr + 64) * 512 + k0 + kk4);
            pb  = *(const float4*)(W + (size_t)(k0 + bk) * 64 + bcol);
        }
        #pragma unroll
        for (int kk = 0; kk < 16; kk++)
            mma_step(acc2, &As[cur][kk][0], &Bs[cur][kk][0], ty, tx);
        if (t + 1 < NTILES) {
            int nb = cur ^ 1;
            As[nb][kk4 + 0][mr] = pa0.x; As[nb][kk4 + 1][mr] = pa0.y;
            As[nb][kk4 + 2][mr] = pa0.z; As[nb][kk4 + 3][mr] = pa0.w;
            As[nb][kk4 + 0][mr + 64] = pa1.x; As[nb][kk4 + 1][mr + 64] = pa1.y;
            As[nb][kk4 + 2][mr + 64] = pa1.z; As[nb][kk4 + 3][mr + 64] = pa1.w;
            *(float4*)&Bs[nb][bk][bcol] = pb;
        }
    }
    #pragma unroll
    for (int i = 0; i < 8; i++) {
        int m = m0 + ty * 8 + i;
        *(float4*)(C + (size_t)m * 64 + tx * 4) = acc_row(acc2, i);
    }
}

// ================================================================
// K2: scores + double softmax + gumbel  (verbatim)
// ================================================================
__global__ void __launch_bounds__(256) scores_kernel(const float* __restrict__ v) {
    __shared__ __align__(16) float ssc[4][1024];
    __shared__ __align__(16) float stile[64][65];
    __shared__ float swq[4][64];
    __shared__ float sv[64];
    __shared__ float sred[8];
    int tid = threadIdx.x;
    int n  = blockIdx.x >> 4;
    int tg = blockIdx.x & 15;
    int t0 = tg * 4;

    if (tid < 64) sv[tid] = v[tid];
    {
        int q = tid >> 6, d = tid & 63;
        swq[q][d] = g_wq[(size_t)(n * 64 + t0 + q) * 64 + d];
    }
    __syncthreads();

    int sloc = tid & 63;
    int tq = tid >> 6;
    for (int tile = 0; tile < 16; tile++) {
        int s0 = tile * 64;
        #pragma unroll
        for (int i = 0; i < 4; i++) {
            int e = i * 1024 + tid * 4;
            int row = e >> 6, col = e & 63;
            float4 a = *(const float4*)(g_uh + (size_t)(n * 1024 + s0 + row) * 64 + col);
            stile[row][col + 0] = a.x; stile[row][col + 1] = a.y;
            stile[row][col + 2] = a.z; stile[row][col + 3] = a.w;
        }
        __syncthreads();
        float accv = 0.f;
        #pragma unroll
        for (int d = 0; d < 64; d++)
            accv = fmaf(sv[d], tanh_hw(swq[tq][d] + stile[sloc][d]), accv);
        ssc[tq][s0 + sloc] = accv;
        __syncthreads();
    }

    for (int q = 0; q < 4; q++) {
        int t = t0 + q;
        unsigned base = (unsigned)(n * 64 + t) * 1024u;
        float lv[4];
        #pragma unroll
        for (int j = 0; j < 4; j++) lv[j] = ssc[q][tid + j * 256];

        float m = fmaxf(fmaxf(lv[0], lv[1]), fmaxf(lv[2], lv[3]));
        m = block_reduce_max(m, sred, tid);
        float s = 0.f;
        #pragma unroll
        for (int j = 0; j < 4; j++) s += __expf(lv[j] - m);
        s = block_reduce_sum(s, sred, tid);
        float L = __logf(s);

        float ys[4];
        #pragma unroll
        for (int j = 0; j < 4; j++) {
            unsigned idx = base + (unsigned)(tid + j * 256);
            float la = lv[j] - m - L;
            g_alpha[idx] = __expf(la);
            float gn = gumbel_noise(idx);
            ys[j] = (la + gn) * 2.0f;
        }
        float m2 = fmaxf(fmaxf(ys[0], ys[1]), fmaxf(ys[2], ys[3]));
        m2 = block_reduce_max(m2, sred, tid);
        float s2 = 0.f;
        #pragma unroll
        for (int j = 0; j < 4; j++) s2 += __expf(ys[j] - m2);
        s2 = block_reduce_sum(s2, sred, tid);
        float inv = __fdividef(1.0f, s2);
        #pragma unroll
        for (int j = 0; j < 4; j++)
            g_yal[base + tid + j * 256] = __expf(ys[j] - m2) * inv;
    }
}

// ================================================================
// K3: contexts, split-K2, 128x128 tile, 8x8 FFMA2.
// grid (4 ntile, 16 n, 2 ks), 256 thr.
// ================================================================
__global__ void __launch_bounds__(256) ctx_kernel(const float* __restrict__ mem) {
    __shared__ __align__(16) float As[2][16][132];
    __shared__ __align__(16) float Bs[2][16][128];
    int tid = threadIdx.x;
    int tx = tid & 15, ty = tid >> 4;
    int n  = blockIdx.y;
    int n0 = blockIdx.x * 128;
    int ks = blockIdx.z;
    int kbase = ks * 512;
    const float* B = mem + (size_t)n * SLEN * SRCD + (size_t)kbase * 512;

    // A loads: 2 float4/thread: f = tid + i*256 -> row = f>>2 (0..127), kq4=(f&3)*4
    int a_row0 = tid >> 2;            // 0..63  (alpha rows)
    int a_row1 = a_row0 + 64;         // 64..127 (yal rows)
    int a_kq4  = (tid & 3) * 4;
    const float* arowp0 = g_alpha + (size_t)n * 65536 + kbase + (size_t)a_row0 * 1024;
    const float* arowp1 = g_yal   + (size_t)n * 65536 + kbase + (size_t)a_row0 * 1024;
    // B loads: 2 float4/thread: f = tid + i*256 -> kk = f>>5 (0..15), c4=(f&31)*4
    int b_kk0 = tid >> 5;             // 0..7
    int b_c4  = (tid & 31) * 4;

    float4 pa0, pa1, pb0, pb1;
    pa0 = *(const float4*)(arowp0 + a_kq4);
    pa1 = *(const float4*)(arowp1 + a_kq4);
    pb0 = *(const float4*)(B + (size_t)b_kk0 * 512 + n0 + b_c4);
    pb1 = *(const float4*)(B + (size_t)(b_kk0 + 8) * 512 + n0 + b_c4);

    {
        As[0][a_kq4 + 0][a_row0] = pa0.x; As[0][a_kq4 + 1][a_row0] = pa0.y;
        As[0][a_kq4 + 2][a_row0] = pa0.z; As[0][a_kq4 + 3][a_row0] = pa0.w;
        As[0][a_kq4 + 0][a_row1] = pa1.x; As[0][a_kq4 + 1][a_row1] = pa1.y;
        As[0][a_kq4 + 2][a_row1] = pa1.z; As[0][a_kq4 + 3][a_row1] = pa1.w;
        *(float4*)&Bs[0][b_kk0][b_c4] = pb0;
        *(float4*)&Bs[0][b_kk0 + 8][b_c4] = pb1;
    }

    u64 acc2[4][8];
    #pragma unroll
    for (int i = 0; i < 4; i++)
        #pragma unroll
        for (int j = 0; j < 8; j++) acc2[i][j] = 0ull;

    const int NTILES = 32;            // 32*16 = 512 K per CTA
    #pragma unroll 1
    for (int t = 0; t < NTILES; t++) {
        __syncthreads();
        int cur = t & 1;
        if (t + 1 < NTILES) {
            int k0 = (t + 1) * 16;
            pa0 = *(const float4*)(arowp0 + k0 + a_kq4);
            pa1 = *(const float4*)(arowp1 + k0 + a_kq4);
            pb0 = *(const float4*)(B + (size_t)(k0 + b_kk0) * 512 + n0 + b_c4);
            pb1 = *(const float4*)(B + (size_t)(k0 + b_kk0 + 8) * 512 + n0 + b_c4);
        }
        #pragma unroll
        for (int kk = 0; kk < 16; kk++)
            mma_step8(acc2, &As[cur][kk][0], &Bs[cur][kk][0], ty, tx);
        if (t + 1 < NTILES) {
            int nb = cur ^ 1;
            As[nb][a_kq4 + 0][a_row0] = pa0.x; As[nb][a_kq4 + 1][a_row0] = pa0.y;
            As[nb][a_kq4 + 2][a_row0] = pa0.z; As[nb][a_kq4 + 3][a_row0] = pa0.w;
            As[nb][a_kq4 + 0][a_row1] = pa1.x; As[nb][a_kq4 + 1][a_row1] = pa1.y;
            As[nb][a_kq4 + 2][a_row1] = pa1.z; As[nb][a_kq4 + 3][a_row1] = pa1.w;
            *(float4*)&Bs[nb][b_kk0][b_c4] = pb0;
            *(float4*)&Bs[nb][b_kk0 + 8][b_c4] = pb1;
        }
    }
    #pragma unroll
    for (int i = 0; i < 8; i++) {
        int m = ty * 8 + i;
        int branch = m >> 6;
        int r = m & 63;
        float* dst = g_ctxp + (((size_t)ks * 2 + branch) * NT + (size_t)n * 64 + r) * 512
                     + n0 + tx * 8;
        float4 lo, hi;
        acc_row8(acc2, i, lo, hi);
        *(float4*)dst = lo;
        *(float4*)(dst + 4) = hi;
    }
}

// ================================================================
// K4: out GEMMs, 128x128 tile, 8x8 FFMA2. grid (8 mtile, 4 ntile, 3)
//   z=0: g_po_in     = input   @ Wout[0:512]
//   z=1: g_po_ctx[0] = (ctxp0b0 + ctxp1b0) @ Wout[512:1024]
//   z=2: g_po_ctx[1] = (ctxp0b1 + ctxp1b1) @ Wout[512:1024]
// ================================================================
__global__ void __launch_bounds__(256) out_gemm_kernel(const float* __restrict__ input,
                                                       const float* __restrict__ Wout) {
    __shared__ __align__(16) float As[2][16][132];
    __shared__ __align__(16) float Bs[2][16][128];
    int tid = threadIdx.x;
    int tx = tid & 15, ty = tid >> 4;
    int z  = blockIdx.z;
    int m0 = blockIdx.x * 128;
    int n0 = blockIdx.y * 128;
    const float* Bw = Wout + ((z == 0) ? 0 : (size_t)512 * 512);
    float* D = (z == 0) ? g_po_in : (g_po_ctx + (size_t)(z - 1) * NT * 512);
    int br = (z == 0) ? 0 : (z - 1);
    const float* P0 = g_ctxp + (size_t)(0 * 2 + br) * NT * 512;
    const float* P1 = g_ctxp + (size_t)(1 * 2 + br) * NT * 512;

    int a_row0 = tid >> 2;            // 0..63
    int a_row1 = a_row0 + 64;
    int a_kq4  = (tid & 3) * 4;
    int b_kk0 = tid >> 5;
    int b_c4  = (tid & 31) * 4;

    float4 pa0, pa1, pb0, pb1;
    if (z == 0) {
        pa0 = *(const float4*)(input + (size_t)(m0 + a_row0) * 512 + a_kq4);
        pa1 = *(const float4*)(input + (size_t)(m0 + a_row1) * 512 + a_kq4);
    } else {
        float4 u0 = *(const float4*)(P0 + (size_t)(m0 + a_row0) * 512 + a_kq4);
        float4 w0 = *(const float4*)(P1 + (size_t)(m0 + a_row0) * 512 + a_kq4);
        float4 u1 = *(const float4*)(P0 + (size_t)(m0 + a_row1) * 512 + a_kq4);
        float4 w1 = *(const float4*)(P1 + (size_t)(m0 + a_row1) * 512 + a_kq4);
        pa0 = make_float4(u0.x + w0.x, u0.y + w0.y, u0.z + w0.z, u0.w + w0.w);
        pa1 = make_float4(u1.x + w1.x, u1.y + w1.y, u1.z + w1.z, u1.w + w1.w);
    }
    pb0 = *(const float4*)(Bw + (size_t)b_kk0 * 512 + n0 + b_c4);
    pb1 = *(const float4*)(Bw + (size_t)(b_kk0 + 8) * 512 + n0 + b_c4);

    As[0][a_kq4 + 0][a_row0] = pa0.x; As[0][a_kq4 + 1][a_row0] = pa0.y;
    As[0][a_kq4 + 2][a_row0] = pa0.z; As[0][a_kq4 + 3][a_row0] = pa0.w;
    As[0][a_kq4 + 0][a_row1] = pa1.x; As[0][a_kq4 + 1][a_row1] = pa1.y;
    As[0][a_kq4 + 2][a_row1] = pa1.z; As[0][a_kq4 + 3][a_row1] = pa1.w;
    *(float4*)&Bs[0][b_kk0][b_c4] = pb0;
    *(float4*)&Bs[0][b_kk0 + 8][b_c4] = pb1;

    u64 acc2[4][8];
    #pragma unroll
    for (int i = 0; i < 4; i++)
        #pragma unroll
        for (int j = 0; j < 8; j++) acc2[i][j] = 0ull;

    const int NTILES = 32;
    #pragma unroll 1
    for (int t = 0; t < NTILES; t++) {
        __syncthreads();
        int cur = t & 1;
        if (t + 1 < NTILES) {
            int k0 = (t + 1) * 16;
            if (z == 0) {
                pa0 = *(const float4*)(input + (size_t)(m0 + a_row0) * 512 + k0 + a_kq4);
                pa1 = *(const float4*)(input + (size_t)(m0 + a_row1) * 512 + k0 + a_kq4);
            } else {
                float4 u0 = *(const float4*)(P0 + (size_t)(m0 + a_row0) * 512 + k0 + a_kq4);
                float4 w0 = *(const float4*)(P1 + (size_t)(m0 + a_row0) * 512 + k0 + a_kq4);
                float4 u1 = *(const float4*)(P0 + (size_t)(m0 + a_row1) * 512 + k0 + a_kq4);
                float4 w1 = *(const float4*)(P1 + (size_t)(m0 + a_row1) * 512 + k0 + a_kq4);
                pa0 = make_float4(u0.x + w0.x, u0.y + w0.y, u0.z + w0.z, u0.w + w0.w);
                pa1 = make_float4(u1.x + w1.x, u1.y + w1.y, u1.z + w1.z, u1.w + w1.w);
            }
            pb0 = *(const float4*)(Bw + (size_t)(k0 + b_kk0) * 512 + n0 + b_c4);
            pb1 = *(const float4*)(Bw + (size_t)(k0 + b_kk0 + 8) * 512 + n0 + b_c4);
        }
        #pragma unroll
        for (int kk = 0; kk < 16; kk++)
            mma_step8(acc2, &As[cur][kk][0], &Bs[cur][kk][0], ty, tx);
        if (t + 1 < NTILES) {
            int nb = cur ^ 1;
            As[nb][a_kq4 + 0][a_row0] = pa0.x; As[nb][a_kq4 + 1][a_row0] = pa0.y;
            As[nb][a_kq4 + 2][a_row0] = pa0.z; As[nb][a_kq4 + 3][a_row0] = pa0.w;
            As[nb][a_kq4 + 0][a_row1] = pa1.x; As[nb][a_kq4 + 1][a_row1] = pa1.y;
            As[nb][a_kq4 + 2][a_row1] = pa1.z; As[nb][a_kq4 + 3][a_row1] = pa1.w;
            *(float4*)&Bs[nb][b_kk0][b_c4] = pb0;
            *(float4*)&Bs[nb][b_kk0 + 8][b_c4] = pb1;
        }
    }
    #pragma unroll
    for (int i = 0; i < 8; i++) {
        int m = m0 + ty * 8 + i;
        float* dst = D + (size_t)m * 512 + n0 + tx * 8;
        float4 lo, hi;
        acc_row8(acc2, i, lo, hi);
        *(float4*)dst = lo;
        *(float4*)(dst + 4) = hi;
    }
}

// K4b: out = tanh(po_in + po_ctx + b)
__global__ void __launch_bounds__(256) out_epi_kernel(const float* __restrict__ bout,
                                                      float* __restrict__ out) {
    size_t e = ((size_t)blockIdx.x * 256 + threadIdx.x);     // float4 index
    size_t rem = e & ((size_t)NT * 512 / 4 - 1);             // within branch
    size_t br  = e >> 17;                                    // NT*512/4 = 131072
    int col = (int)((rem & 127) * 4);
    float4 pi = *(const float4*)(g_po_in + rem * 4);
    float4 pc = *(const float4*)(g_po_ctx + br * (size_t)NT * 512 + rem * 4);
    float4 bb = *(const float4*)(bout + col);
    float4 o;
    o.x = tanh_acc(pi.x + pc.x + bb.x);
    o.y = tanh_acc(pi.y + pc.y + bb.y);
    o.z = tanh_acc(pi.z + pc.z + bb.z);
    o.w = tanh_acc(pi.w + pc.w + bb.w);
    *(float4*)(out + e * 4) = o;
}

// ---------------- launch ----------------
extern "C" void kernel_launch(void* const* d_in, const int* in_sizes, int n_in,
                              void* d_out, int out_size) {
    const float* input = (const float*)d_in[0];
    const float* mem   = (const float*)d_in[1];
    const float* W_q   = (const float*)d_in[2];
    const float* W_ctx = (const float*)d_in[3];
    const float* v     = (const float*)d_in[4];
    const float* W_out = (const float*)d_in[5];
    const float* b_out = (const float*)d_in[6];
    float* out = (float*)d_out;

    float *p_wq = nullptr, *p_uh = nullptr;
    cudaGetSymbolAddress((void**)&p_wq, g_wq);
    cudaGetSymbolAddress((void**)&p_uh, g_uh);

    proj_kernel<<<NT / 128, 256>>>(input, W_q, p_wq);        // wq  [1024,64]
    proj_kernel<<<NS / 128, 256>>>(mem, W_ctx, p_uh);        // uh  [16384,64]
    scores_kernel<<<256, 256>>>(v);                          // alpha, y_align
    ctx_kernel<<<dim3(4, 16, 2), 256>>>(mem);                // ctx partials (split-K2)
    out_gemm_kernel<<<dim3(8, 4, 3), 256>>>(input, W_out);   // 3 GEMM parts
    out_epi_kernel<<<(2 * NT * 512 / 4) / 256, 256>>>(b_out, out);
}

// round 17
// speedup vs baseline: 1.1039x; 1.1039x over previous
#include <cuda_runtime.h>
#include <math.h>
#include <string.h>

#define NBATCH 16
#define TLEN   64
#define SLEN   1024
#define SRCD   512
#define TGTD   512
#define NT     1024
#define NS     16384
#define NTS    1048576
#define PLANE  ((size_t)NT * 512)      // 524288 floats

typedef unsigned long long u64;

#if defined(__CUDA_ARCH__) && (defined(__CUDA_ARCH_FEAT_SM103_ALL) || defined(__CUDA_ARCH_FEAT_SM100_ALL))
#define HAS_X2 1
#else
#define HAS_X2 0
#endif

// ---------------- device scratch ----------------
__device__ __align__(16) float g_wq[NT*64];            // [1024,64]
__device__ __align__(16) float g_uh[NS*64];            // [16384,64]
__device__ __align__(16) float g_alpha[NTS];           // [16,64,1024]
__device__ __align__(16) float g_yal[NTS];             // [16,64,1024]
__device__ __align__(16) float g_ctxp[4*2*NT*SRCD];    // [ks4][branch][1024][512]
__device__ __align__(16) float g_po[3*2*NT*TGTD];      // [part3][ks2][1024][512]

// ---------------- packed fp32 helpers ----------------
__device__ __forceinline__ void fma2(u64& d, u64 a, u64 b) {
#if HAS_X2
    asm("fma.rn.f32x2 %0, %1, %2, %0;" : "+l"(d) : "l"(a), "l"(b));
#else
    float2 dd, aa, bb;
    memcpy(&dd, &d, 8); memcpy(&aa, &a, 8); memcpy(&bb, &b, 8);
    dd.x = fmaf(aa.x, bb.x, dd.x);
    dd.y = fmaf(aa.y, bb.y, dd.y);
    memcpy(&d, &dd, 8);
#endif
}
__device__ __forceinline__ u64 bcast2(float x) {
    float2 t = make_float2(x, x);
    u64 d; memcpy(&d, &t, 8);
    return d;
}

// ---------------- helpers ----------------
__device__ __forceinline__ float tanh_hw(float x) {
    float y;
    asm("tanh.approx.f32 %0, %1;" : "=f"(y) : "f"(x));
    return y;
}
__device__ __forceinline__ float tanh_acc(float x) {
    float e = __expf(2.0f * x);
    return 1.0f - __fdividef(2.0f, e + 1.0f);
}

// JAX threefry2x32, key=(0,42), partitionable: bits = out0 ^ out1
__device__ __forceinline__ unsigned threefry_bits(unsigned idx) {
    const unsigned ks0 = 0u, ks1 = 42u;
    const unsigned ks2 = 0x1BD11BDAu ^ ks0 ^ ks1;
    unsigned x0 = ks0;
    unsigned x1 = idx + ks1;
#define TF_ROUND(r) { x0 += x1; x1 = (x1 << (r)) | (x1 >> (32 - (r))); x1 ^= x0; }
    TF_ROUND(13) TF_ROUND(15) TF_ROUND(26) TF_ROUND(6)
    x0 += ks1; x1 += ks2 + 1u;
    TF_ROUND(17) TF_ROUND(29) TF_ROUND(16) TF_ROUND(24)
    x0 += ks2; x1 += ks0 + 2u;
    TF_ROUND(13) TF_ROUND(15) TF_ROUND(26) TF_ROUND(6)
    x0 += ks0; x1 += ks1 + 3u;
    TF_ROUND(17) TF_ROUND(29) TF_ROUND(16) TF_ROUND(24)
    x0 += ks1; x1 += ks2 + 4u;
    TF_ROUND(13) TF_ROUND(15) TF_ROUND(26) TF_ROUND(6)
    x0 += ks2; x1 += ks0 + 5u;
#undef TF_ROUND
    return x0 ^ x1;
}

__device__ __forceinline__ float gumbel_noise(unsigned idx) {
    unsigned b = threefry_bits(idx);
    float u = __uint_as_float((b >> 9) | 0x3f800000u) - 1.0f;
    float inner = -__logf(u + 1e-20f) + 1e-20f;
    return -__logf(inner);
}

__device__ __forceinline__ float block_reduce_max(float v, float* sred, int tid) {
    #pragma unroll
    for (int o = 16; o > 0; o >>= 1) v = fmaxf(v, __shfl_xor_sync(0xffffffffu, v, o));
    if ((tid & 31) == 0) sred[tid >> 5] = v;
    __syncthreads();
    float r = sred[0];
    #pragma unroll
    for (int i = 1; i < 8; i++) r = fmaxf(r, sred[i]);
    __syncthreads();
    return r;
}

__device__ __forceinline__ float block_reduce_sum(float v, float* sred, int tid) {
    #pragma unroll
    for (int o = 16; o > 0; o >>= 1) v += __shfl_xor_sync(0xffffffffu, v, o);
    if ((tid & 31) == 0) sred[tid >> 5] = v;
    __syncthreads();
    float r = 0.0f;
    #pragma unroll
    for (int i = 0; i < 8; i++) r += sred[i];
    __syncthreads();
    return r;
}

// 8x4 packed step (R14 WIN config)
__device__ __forceinline__ void mma_step(u64 acc2[4][4], const float* As_kk,
                                         const float* Bs_kk, int ty, int tx) {
    float af[8], bf[4];
    *(float4*)&af[0] = *(const float4*)(As_kk + ty * 8);
    *(float4*)&af[4] = *(const float4*)(As_kk + ty * 8 + 4);
    *(float4*)&bf[0] = *(const float4*)(Bs_kk + tx * 4);
    u64 af2[4];
    memcpy(af2, af, 32);
    u64 bf2[4];
    #pragma unroll
    for (int j = 0; j < 4; j++) bf2[j] = bcast2(bf[j]);
    #pragma unroll
    for (int ip = 0; ip < 4; ip++)
        #pragma unroll
        for (int j = 0; j < 4; j++)
            fma2(acc2[ip][j], af2[ip], bf2[j]);
}
__device__ __forceinline__ float4 acc_row(const u64 acc2[4][4], int i) {
    float r[4];
    #pragma unroll
    for (int j = 0; j < 4; j++) {
        float2 t; memcpy(&t, &acc2[i >> 1][j], 8);
        r[j] = (i & 1) ? t.y : t.x;
    }
    return make_float4(r[0], r[1], r[2], r[3]);
}

// ================================================================
// K1: projections  C[M,64] = A[M,512] @ W[512,64]  (R14 verbatim)
// ================================================================
__global__ void __launch_bounds__(256) proj_kernel(const float* __restrict__ A,
                                                   const float* __restrict__ W,
                                                   float* __restrict__ C) {
    __shared__ __align__(16) float As[2][16][132];
    __shared__ __align__(16) float Bs[2][16][64];
    int tid = threadIdx.x;
    int tx = tid & 15, ty = tid >> 4;
    int m0 = blockIdx.x * 128;
    int kk4 = (tid & 3) * 4, mr = tid >> 2;
    int bcol = (tid & 15) * 4, bk = tid >> 4;

    float4 pa0, pa1, pb;
    pa0 = *(const float4*)(A + (size_t)(m0 + mr) * 512 + kk4);
    pa1 = *(const float4*)(A + (size_t)(m0 + mr + 64) * 512 + kk4);
    pb  = *(const float4*)(W + (size_t)bk * 64 + bcol);
    As[0][kk4 + 0][mr] = pa0.x; As[0][kk4 + 1][mr] = pa0.y;
    As[0][kk4 + 2][mr] = pa0.z; As[0][kk4 + 3][mr] = pa0.w;
    As[0][kk4 + 0][mr + 64] = pa1.x; As[0][kk4 + 1][mr + 64] = pa1.y;
    As[0][kk4 + 2][mr + 64] = pa1.z; As[0][kk4 + 3][mr + 64] = pa1.w;
    *(float4*)&Bs[0][bk][bcol] = pb;

    u64 acc2[4][4];
    #pragma unroll
    for (int i = 0; i < 4; i++)
        #pragma unroll
        for (int j = 0; j < 4; j++) acc2[i][j] = 0ull;

    const int NTILES = 32;
    #pragma unroll 1
    for (int t = 0; t < NTILES; t++) {
        __syncthreads();
        int cur = t & 1;
        if (t + 1 < NTILES) {
            int k0 = (t + 1) * 16;
            pa0 = *(const float4*)(A + (size_t)(m0 + mr) * 512 + k0 + kk4);
            pa1 = *(const float4*)(A + (size_t)(m0 + mr + 64) * 512 + k0 + kk4);
            pb  = *(const float4*)(W + (size_t)(k0 + bk) * 64 + bcol);
        }
        #pragma unroll
        for (int kk = 0; kk < 16; kk++)
            mma_step(acc2, &As[cur][kk][0], &Bs[cur][kk][0], ty, tx);
        if (t + 1 < NTILES) {
            int nb = cur ^ 1;
            As[nb][kk4 + 0][mr] = pa0.x; As[nb][kk4 + 1][mr] = pa0.y;
            As[nb][kk4 + 2][mr] = pa0.z; As[nb][kk4 + 3][mr] = pa0.w;
            As[nb][kk4 + 0][mr + 64] = pa1.x; As[nb][kk4 + 1][mr + 64] = pa1.y;
            As[nb][kk4 + 2][mr + 64] = pa1.z; As[nb][kk4 + 3][mr + 64] = pa1.w;
            *(float4*)&Bs[nb][bk][bcol] = pb;
        }
    }
    #pragma unroll
    for (int i = 0; i < 8; i++) {
        int m = m0 + ty * 8 + i;
        *(float4*)(C + (size_t)m * 64 + tx * 4) = acc_row(acc2, i);
    }
}

// ================================================================
// K2: scores + double softmax + gumbel  (verbatim)
// ================================================================
__global__ void __launch_bounds__(256) scores_kernel(const float* __restrict__ v) {
    __shared__ __align__(16) float ssc[4][1024];
    __shared__ __align__(16) float stile[64][65];
    __shared__ float swq[4][64];
    __shared__ float sv[64];
    __shared__ float sred[8];
    int tid = threadIdx.x;
    int n  = blockIdx.x >> 4;
    int tg = blockIdx.x & 15;
    int t0 = tg * 4;

    if (tid < 64) sv[tid] = v[tid];
    {
        int q = tid >> 6, d = tid & 63;
        swq[q][d] = g_wq[(size_t)(n * 64 + t0 + q) * 64 + d];
    }
    __syncthreads();

    int sloc = tid & 63;
    int tq = tid >> 6;
    for (int tile = 0; tile < 16; tile++) {
        int s0 = tile * 64;
        #pragma unroll
        for (int i = 0; i < 4; i++) {
            int e = i * 1024 + tid * 4;
            int row = e >> 6, col = e & 63;
            float4 a = *(const float4*)(g_uh + (size_t)(n * 1024 + s0 + row) * 64 + col);
            stile[row][col + 0] = a.x; stile[row][col + 1] = a.y;
            stile[row][col + 2] = a.z; stile[row][col + 3] = a.w;
        }
        __syncthreads();
        float accv = 0.f;
        #pragma unroll
        for (int d = 0; d < 64; d++)
            accv = fmaf(sv[d], tanh_hw(swq[tq][d] + stile[sloc][d]), accv);
        ssc[tq][s0 + sloc] = accv;
        __syncthreads();
    }

    for (int q = 0; q < 4; q++) {
        int t = t0 + q;
        unsigned base = (unsigned)(n * 64 + t) * 1024u;
        float lv[4];
        #pragma unroll
        for (int j = 0; j < 4; j++) lv[j] = ssc[q][tid + j * 256];

        float m = fmaxf(fmaxf(lv[0], lv[1]), fmaxf(lv[2], lv[3]));
        m = block_reduce_max(m, sred, tid);
        float s = 0.f;
        #pragma unroll
        for (int j = 0; j < 4; j++) s += __expf(lv[j] - m);
        s = block_reduce_sum(s, sred, tid);
        float L = __logf(s);

        float ys[4];
        #pragma unroll
        for (int j = 0; j < 4; j++) {
            unsigned idx = base + (unsigned)(tid + j * 256);
            float la = lv[j] - m - L;
            g_alpha[idx] = __expf(la);
            float gn = gumbel_noise(idx);
            ys[j] = (la + gn) * 2.0f;
        }
        float m2 = fmaxf(fmaxf(ys[0], ys[1]), fmaxf(ys[2], ys[3]));
        m2 = block_reduce_max(m2, sred, tid);
        float s2 = 0.f;
        #pragma unroll
        for (int j = 0; j < 4; j++) s2 += __expf(ys[j] - m2);
        s2 = block_reduce_sum(s2, sred, tid);
        float inv = __fdividef(1.0f, s2);
        #pragma unroll
        for (int j = 0; j < 4; j++)
            g_yal[base + tid + j * 256] = __expf(ys[j] - m2) * inv;
    }
}

// ================================================================
// K3: contexts, split-K4, BK=16, 8x4 FFMA2.
// grid (8 ntile, 16 n, 4 ks), K=256/CTA. Partials to g_ctxp[ks][branch].
// ================================================================
__global__ void __launch_bounds__(256) ctx_kernel(const float* __restrict__ mem) {
    __shared__ __align__(16) float As[2][16][132];
    __shared__ __align__(16) float Bs[2][16][64];
    int tid = threadIdx.x;
    int tx = tid & 15, ty = tid >> 4;
    int n  = blockIdx.y;
    int n0 = blockIdx.x * 64;
    int ks = blockIdx.z;
    int kbase = ks * 256;
    const float* B = mem + (size_t)n * SLEN * SRCD;
    int kk4 = (tid & 3) * 4, mr = tid >> 2;
    int bcol = (tid & 15) * 4, bk = tid >> 4;
    const float* arow0 = g_alpha + (size_t)n * 65536 + kbase + (size_t)mr * 1024;
    const float* arow1 = g_yal   + (size_t)n * 65536 + kbase + (size_t)mr * 1024;

    float4 pa0, pa1, pb;
    pa0 = *(const float4*)(arow0 + kk4);
    pa1 = *(const float4*)(arow1 + kk4);
    pb  = *(const float4*)(B + (size_t)(kbase + bk) * 512 + n0 + bcol);
    As[0][kk4 + 0][mr] = pa0.x; As[0][kk4 + 1][mr] = pa0.y;
    As[0][kk4 + 2][mr] = pa0.z; As[0][kk4 + 3][mr] = pa0.w;
    As[0][kk4 + 0][mr + 64] = pa1.x; As[0][kk4 + 1][mr + 64] = pa1.y;
    As[0][kk4 + 2][mr + 64] = pa1.z; As[0][kk4 + 3][mr + 64] = pa1.w;
    *(float4*)&Bs[0][bk][bcol] = pb;

    u64 acc2[4][4];
    #pragma unroll
    for (int i = 0; i < 4; i++)
        #pragma unroll
        for (int j = 0; j < 4; j++) acc2[i][j] = 0ull;

    const int NTILES = 16;              // 16 * 16 = 256 K
    #pragma unroll 1
    for (int t = 0; t < NTILES; t++) {
        __syncthreads();
        int cur = t & 1;
        if (t + 1 < NTILES) {
            int k0 = (t + 1) * 16;
            pa0 = *(const float4*)(arow0 + k0 + kk4);
            pa1 = *(const float4*)(arow1 + k0 + kk4);
            pb  = *(const float4*)(B + (size_t)(kbase + k0 + bk) * 512 + n0 + bcol);
        }
        #pragma unroll
        for (int kk = 0; kk < 16; kk++)
            mma_step(acc2, &As[cur][kk][0], &Bs[cur][kk][0], ty, tx);
        if (t + 1 < NTILES) {
            int nb = cur ^ 1;
            As[nb][kk4 + 0][mr] = pa0.x; As[nb][kk4 + 1][mr] = pa0.y;
            As[nb][kk4 + 2][mr] = pa0.z; As[nb][kk4 + 3][mr] = pa0.w;
            As[nb][kk4 + 0][mr + 64] = pa1.x; As[nb][kk4 + 1][mr + 64] = pa1.y;
            As[nb][kk4 + 2][mr + 64] = pa1.z; As[nb][kk4 + 3][mr + 64] = pa1.w;
            *(float4*)&Bs[nb][bk][bcol] = pb;
        }
    }
    #pragma unroll
    for (int i = 0; i < 8; i++) {
        int m = ty * 8 + i;
        int branch = m >> 6;
        int r = m & 63;
        float* dst = g_ctxp + (((size_t)ks * 2 + branch) * NT + (size_t)n * 64 + r) * 512
                     + n0 + tx * 4;
        *(float4*)dst = acc_row(acc2, i);
    }
}

// ================================================================
// K4: out GEMMs, split-K2, grid (8 mtile, 8 ntile, 6 = part*2+ks)
//   part 0: A = input;  part 1/2: A = sum of 4 ctx partials (branch part-1)
//   B = Wout[part==0 ? top : bottom], rows kbase..kbase+256
//   D = g_po[part][ks]
// ================================================================
__global__ void __launch_bounds__(256) out_gemm_kernel(const float* __restrict__ input,
                                                       const float* __restrict__ Wout) {
    __shared__ __align__(16) float As[2][16][132];
    __shared__ __align__(16) float Bs[2][16][64];
    int tid = threadIdx.x;
    int tx = tid & 15, ty = tid >> 4;
    int part = blockIdx.z >> 1;
    int ks   = blockIdx.z & 1;
    int kbase = ks * 256;
    int m0 = blockIdx.x * 128;
    int n0 = blockIdx.y * 64;
    const float* B = Wout + ((part == 0) ? 0 : (size_t)512 * 512) + (size_t)kbase * 512;
    float* D = g_po + ((size_t)part * 2 + ks) * PLANE;
    int br = (part == 0) ? 0 : (part - 1);
    const float* P0 = g_ctxp + ((size_t)0 * 2 + br) * PLANE + kbase;
    const float* P1 = g_ctxp + ((size_t)1 * 2 + br) * PLANE + kbase;
    const float* P2 = g_ctxp + ((size_t)2 * 2 + br) * PLANE + kbase;
    const float* P3 = g_ctxp + ((size_t)3 * 2 + br) * PLANE + kbase;
    int kk4 = (tid & 3) * 4, mr = tid >> 2;
    int bcol = (tid & 15) * 4, bk = tid >> 4;

    float4 pa0, pa1, pb;
    #define LOAD_A(dst, row, koff)                                                   \
        if (part == 0) {                                                             \
            dst = *(const float4*)(input + (size_t)(row) * 512 + kbase + (koff));    \
        } else {                                                                     \
            float4 u0 = *(const float4*)(P0 + (size_t)(row) * 512 + (koff));         \
            float4 u1 = *(const float4*)(P1 + (size_t)(row) * 512 + (koff));         \
            float4 u2 = *(const float4*)(P2 + (size_t)(row) * 512 + (koff));         \
            float4 u3 = *(const float4*)(P3 + (size_t)(row) * 512 + (koff));         \
            dst = make_float4(u0.x + u1.x + u2.x + u3.x, u0.y + u1.y + u2.y + u3.y,  \
                              u0.z + u1.z + u2.z + u3.z, u0.w + u1.w + u2.w + u3.w); \
        }

    LOAD_A(pa0, m0 + mr, kk4);
    LOAD_A(pa1, m0 + mr + 64, kk4);
    pb = *(const float4*)(B + (size_t)bk * 512 + n0 + bcol);
    As[0][kk4 + 0][mr] = pa0.x; As[0][kk4 + 1][mr] = pa0.y;
    As[0][kk4 + 2][mr] = pa0.z; As[0][kk4 + 3][mr] = pa0.w;
    As[0][kk4 + 0][mr + 64] = pa1.x; As[0][kk4 + 1][mr + 64] = pa1.y;
    As[0][kk4 + 2][mr + 64] = pa1.z; As[0][kk4 + 3][mr + 64] = pa1.w;
    *(float4*)&Bs[0][bk][bcol] = pb;

    u64 acc2[4][4];
    #pragma unroll
    for (int i = 0; i < 4; i++)
        #pragma unroll
        for (int j = 0; j < 4; j++) acc2[i][j] = 0ull;

    const int NTILES = 16;              // 16 * 16 = 256 K
    #pragma unroll 1
    for (int t = 0; t < NTILES; t++) {
        __syncthreads();
        int cur = t & 1;
        if (t + 1 < NTILES) {
            int k0 = (t + 1) * 16;
            LOAD_A(pa0, m0 + mr, k0 + kk4);
            LOAD_A(pa1, m0 + mr + 64, k0 + kk4);
            pb = *(const float4*)(B + (size_t)(k0 + bk) * 512 + n0 + bcol);
        }
        #pragma unroll
        for (int kk = 0; kk < 16; kk++)
            mma_step(acc2, &As[cur][kk][0], &Bs[cur][kk][0], ty, tx);
        if (t + 1 < NTILES) {
            int nb = cur ^ 1;
            As[nb][kk4 + 0][mr] = pa0.x; As[nb][kk4 + 1][mr] = pa0.y;
            As[nb][kk4 + 2][mr] = pa0.z; As[nb][kk4 + 3][mr] = pa0.w;
            As[nb][kk4 + 0][mr + 64] = pa1.x; As[nb][kk4 + 1][mr + 64] = pa1.y;
            As[nb][kk4 + 2][mr + 64] = pa1.z; As[nb][kk4 + 3][mr + 64] = pa1.w;
            *(float4*)&Bs[nb][bk][bcol] = pb;
        }
    }
    #undef LOAD_A
    #pragma unroll
    for (int i = 0; i < 8; i++) {
        int m = m0 + ty * 8 + i;
        *(float4*)(D + (size_t)m * 512 + n0 + tx * 4) = acc_row(acc2, i);
    }
}

// K4b: out = tanh(po_in0+po_in1 + po_ctx[br]0+po_ctx[br]1 + b)
__global__ void __launch_bounds__(256) out_epi_kernel(const float* __restrict__ bout,
                                                      float* __restrict__ out) {
    size_t e = ((size_t)blockIdx.x * 256 + threadIdx.x);     // float4 index
    size_t rem = e & (PLANE / 4 - 1);                        // within branch
    size_t br  = e >> 17;                                    // PLANE/4 = 131072
    int col = (int)((rem & 127) * 4);
    float4 a0 = *(const float4*)(g_po + 0 * PLANE + rem * 4);            // in, ks0
    float4 a1 = *(const float4*)(g_po + 1 * PLANE + rem * 4);            // in, ks1
    float4 c0 = *(const float4*)(g_po + (2 + br * 2 + 0) * PLANE + rem * 4);
    float4 c1 = *(const float4*)(g_po + (2 + br * 2 + 1) * PLANE + rem * 4);
    float4 bb = *(const float4*)(bout + col);
    float4 o;
    o.x = tanh_acc(a0.x + a1.x + c0.x + c1.x + bb.x);
    o.y = tanh_acc(a0.y + a1.y + c0.y + c1.y + bb.y);
    o.z = tanh_acc(a0.z + a1.z + c0.z + c1.z + bb.z);
    o.w = tanh_acc(a0.w + a1.w + c0.w + c1.w + bb.w);
    *(float4*)(out + e * 4) = o;
}

// ---------------- launch ----------------
extern "C" void kernel_launch(void* const* d_in, const int* in_sizes, int n_in,
                              void* d_out, int out_size) {
    const float* input = (const float*)d_in[0];
    const float* mem   = (const float*)d_in[1];
    const float* W_q   = (const float*)d_in[2];
    const float* W_ctx = (const float*)d_in[3];
    const float* v     = (const float*)d_in[4];
    const float* W_out = (const float*)d_in[5];
    const float* b_out = (const float*)d_in[6];
    float* out = (float*)d_out;

    float *p_wq = nullptr, *p_uh = nullptr;
    cudaGetSymbolAddress((void**)&p_wq, g_wq);
    cudaGetSymbolAddress((void**)&p_uh, g_uh);

    proj_kernel<<<NT / 128, 256>>>(input, W_q, p_wq);        // wq  [1024,64]
    proj_kernel<<<NS / 128, 256>>>(mem, W_ctx, p_uh);        // uh  [16384,64]
    scores_kernel<<<256, 256>>>(v);                          // alpha, y_align
    ctx_kernel<<<dim3(8, 16, 4), 256>>>(mem);                // ctx partials (split-K4)
    out_gemm_kernel<<<dim3(8, 8, 6), 256>>>(input, W_out);   // 3 parts x split-K2
    out_epi_kernel<<<(int)(2 * PLANE / 4 / 256), 256>>>(b_out, out);
}